// round 3
// baseline (speedup 1.0000x reference)
#include <cuda_runtime.h>
#include <math.h>

#define B_   2
#define S_   1024
#define H_   4096
#define NH_  32
#define NKV_ 8
#define D_   128
#define MROWS (B_*S_)   // 2048

// Scratch (allocation-free rule: __device__ globals)
__device__ float g_QP[(size_t)MROWS*NH_*D_];   // [b,s,h,d]  2048 x 4096
__device__ float g_KP[(size_t)MROWS*NKV_*D_];  // [b,s,kv,d] 2048 x 1024
__device__ float g_VP[(size_t)MROWS*NKV_*D_];
__device__ float g_AO[(size_t)MROWS*NH_*D_];   // attention out [b,s,h,d]

// ---------------------------------------------------------------------------
// Tiled SGEMM: C[M,N] = A[M,K] * B[K,N], fp32. BM=BN=128, BK=16, 8x8/thread.
// M,N,K must be multiples of 128/128/16 (true for all calls here).
// ---------------------------------------------------------------------------
__global__ __launch_bounds__(256) void sgemm128(
    const float* __restrict__ A, const float* __restrict__ Bm,
    float* __restrict__ C, int M, int N, int K)
{
    __shared__ float As[16][132];   // A tile transposed, +4 pad
    __shared__ float Bs[16][128];
    const int t  = threadIdx.x;
    const int tx = t & 15, ty = t >> 4;
    const int bn0 = blockIdx.x * 128;
    const int bm0 = blockIdx.y * 128;
    const float* Ab = A + (size_t)bm0 * K;
    const float* Bb = Bm + bn0;

    float acc[8][8];
#pragma unroll
    for (int i = 0; i < 8; i++)
#pragma unroll
        for (int j = 0; j < 8; j++) acc[i][j] = 0.f;

    for (int k0 = 0; k0 < K; k0 += 16) {
        // A tile: 128 rows x 16 cols = 512 float4, 2 per thread, transpose into As
#pragma unroll
        for (int r = 0; r < 2; r++) {
            int l = t * 2 + r;
            int m = l >> 2, kq = l & 3;
            float4 v = *(const float4*)(Ab + (size_t)m * K + k0 + kq * 4);
            As[kq*4+0][m] = v.x; As[kq*4+1][m] = v.y;
            As[kq*4+2][m] = v.z; As[kq*4+3][m] = v.w;
        }
        // B tile: 16 rows x 128 cols
#pragma unroll
        for (int r = 0; r < 2; r++) {
            int l = t * 2 + r;
            int k = l >> 5, nq = l & 31;
            *(float4*)&Bs[k][nq*4] = *(const float4*)(Bb + (size_t)(k0 + k) * N + nq * 4);
        }
        __syncthreads();
#pragma unroll
        for (int k = 0; k < 16; k++) {
            float4 a0 = *(float4*)&As[k][ty*8];
            float4 a1 = *(float4*)&As[k][ty*8+4];
            float4 b0 = *(float4*)&Bs[k][tx*8];
            float4 b1 = *(float4*)&Bs[k][tx*8+4];
            float ra[8] = {a0.x,a0.y,a0.z,a0.w,a1.x,a1.y,a1.z,a1.w};
            float rb[8] = {b0.x,b0.y,b0.z,b0.w,b1.x,b1.y,b1.z,b1.w};
#pragma unroll
            for (int i = 0; i < 8; i++)
#pragma unroll
                for (int j = 0; j < 8; j++)
                    acc[i][j] += ra[i] * rb[j];
        }
        __syncthreads();
    }

    float* Cb = C + (size_t)(bm0 + ty*8) * N + bn0 + tx*8;
#pragma unroll
    for (int i = 0; i < 8; i++) {
        *(float4*)&Cb[(size_t)i*N]     = make_float4(acc[i][0],acc[i][1],acc[i][2],acc[i][3]);
        *(float4*)&Cb[(size_t)i*N + 4] = make_float4(acc[i][4],acc[i][5],acc[i][6],acc[i][7]);
    }
}

// ---------------------------------------------------------------------------
// RoPE in place over [ (b,s), h, d ] layout; also folds softmax scale (Q only).
// out[d]    = (x[d]*cos[d]    - x[d+64]*sin[d]   ) * scale   (d < 64)
// out[d+64] = (x[d+64]*cos[d+64] + x[d]*sin[d+64]) * scale
// ---------------------------------------------------------------------------
__global__ void rope_scale_kernel(float* __restrict__ X,
                                  const float* __restrict__ cosT,
                                  const float* __restrict__ sinT,
                                  int nheads, float scale)
{
    int idx = blockIdx.x * blockDim.x + threadIdx.x;
    int total = MROWS * nheads * (D_/2);
    if (idx >= total) return;
    int d    = idx & 63;
    int rest = idx >> 6;
    int h = rest % nheads;
    int m = rest / nheads;               // flattened (b,s)
    float* p = X + ((size_t)m * nheads + h) * D_;
    float q1 = p[d], q2 = p[d+64];
    float c1 = cosT[m*D_ + d],      s1 = sinT[m*D_ + d];
    float c2 = cosT[m*D_ + d + 64], s2 = sinT[m*D_ + d + 64];
    p[d]    = (q1*c1 - q2*s1) * scale;
    p[d+64] = (q2*c2 + q1*s2) * scale;
}

// ---------------------------------------------------------------------------
// Flash attention (causal, fp32). 64x64 tiles, D=128, 256 threads (16x16),
// each thread: 4 S-rows x 4 S-cols, O accumulator 4 rows x 8 cols.
// Q is pre-scaled by 1/sqrt(D). GQA: head h uses kv head h/4.
// ---------------------------------------------------------------------------
#define QS_LD 132
#define KS_LD 132
#define PS_LD 68
#define FLASH_SMEM_FLOATS (64*QS_LD + 64*KS_LD + 64*128 + 64*PS_LD)

__global__ __launch_bounds__(256) void flash_kernel(
    const float* __restrict__ Q, const float* __restrict__ K,
    const float* __restrict__ V, float* __restrict__ O)
{
    extern __shared__ float sm[];
    float* Qs = sm;
    float* Ks = Qs + 64*QS_LD;
    float* Vs = Ks + 64*KS_LD;
    float* Ps = Vs + 64*128;

    const int t  = threadIdx.x;
    const int tx = t & 15, ty = t >> 4;
    const int m0 = blockIdx.x * 64;
    const int bh = blockIdx.y;
    const int b  = bh >> 5;
    const int h  = bh & 31;
    const int kvh = h >> 2;

    const float* Qb = Q + (size_t)b*S_*NH_*D_  + h*D_;
    const float* Kb = K + (size_t)b*S_*NKV_*D_ + kvh*D_;
    const float* Vb = V + (size_t)b*S_*NKV_*D_ + kvh*D_;

    // Load Q tile (64 x 128)
    for (int l = t; l < 64*32; l += 256) {
        int r = l >> 5, c4 = (l & 31) * 4;
        *(float4*)&Qs[r*QS_LD + c4] = *(const float4*)(Qb + (size_t)(m0 + r)*(NH_*D_) + c4);
    }

    float acc[4][8];
#pragma unroll
    for (int i = 0; i < 4; i++)
#pragma unroll
        for (int j = 0; j < 8; j++) acc[i][j] = 0.f;
    float mi[4] = {-1e30f,-1e30f,-1e30f,-1e30f};
    float li[4] = {0.f,0.f,0.f,0.f};

    const int nT = blockIdx.x + 1;          // causal: only tiles with n0 <= m0
    for (int it = 0; it < nT; ++it) {
        int n0 = it * 64;
        // Load K,V tiles (64 x 128 each)
        for (int l = t; l < 64*32; l += 256) {
            int r = l >> 5, c4 = (l & 31) * 4;
            *(float4*)&Ks[r*KS_LD + c4] = *(const float4*)(Kb + (size_t)(n0 + r)*(NKV_*D_) + c4);
            *(float4*)&Vs[r*128 + c4]   = *(const float4*)(Vb + (size_t)(n0 + r)*(NKV_*D_) + c4);
        }
        __syncthreads();

        // S = Q K^T  (scale already folded into Q)
        float s[4][4];
#pragma unroll
        for (int i = 0; i < 4; i++)
#pragma unroll
            for (int j = 0; j < 4; j++) s[i][j] = 0.f;
        for (int k4 = 0; k4 < 32; k4++) {
            float4 qa[4], kb[4];
#pragma unroll
            for (int i = 0; i < 4; i++) qa[i] = *(float4*)&Qs[(ty*4+i)*QS_LD + k4*4];
#pragma unroll
            for (int j = 0; j < 4; j++) kb[j] = *(float4*)&Ks[(tx*4+j)*KS_LD + k4*4];
#pragma unroll
            for (int i = 0; i < 4; i++)
#pragma unroll
                for (int j = 0; j < 4; j++)
                    s[i][j] += qa[i].x*kb[j].x + qa[i].y*kb[j].y
                             + qa[i].z*kb[j].z + qa[i].w*kb[j].w;
        }
        if (n0 == m0) {   // diagonal tile: mask k > q
#pragma unroll
            for (int i = 0; i < 4; i++)
#pragma unroll
                for (int j = 0; j < 4; j++)
                    if (tx*4 + j > ty*4 + i) s[i][j] = -1e30f;
        }

        // Online softmax (row groups shared across tx; reduce over lane bits 0-3)
#pragma unroll
        for (int i = 0; i < 4; i++) {
            float ml = fmaxf(fmaxf(s[i][0], s[i][1]), fmaxf(s[i][2], s[i][3]));
#pragma unroll
            for (int off = 8; off > 0; off >>= 1)
                ml = fmaxf(ml, __shfl_xor_sync(0xffffffffu, ml, off));
            float mnew  = fmaxf(mi[i], ml);
            float alpha = __expf(mi[i] - mnew);
            mi[i] = mnew;
            float4 pr;
            pr.x = __expf(s[i][0] - mnew); pr.y = __expf(s[i][1] - mnew);
            pr.z = __expf(s[i][2] - mnew); pr.w = __expf(s[i][3] - mnew);
            float rsum = pr.x + pr.y + pr.z + pr.w;
            *(float4*)&Ps[(ty*4+i)*PS_LD + tx*4] = pr;
#pragma unroll
            for (int off = 8; off > 0; off >>= 1)
                rsum += __shfl_xor_sync(0xffffffffu, rsum, off);
            li[i] = li[i]*alpha + rsum;
#pragma unroll
            for (int j = 0; j < 8; j++) acc[i][j] *= alpha;
        }
        __syncthreads();

        // O += P V  (P: 64x64 in smem, V: 64x128 in smem)
        for (int k4 = 0; k4 < 16; k4++) {
            float4 p4[4];
#pragma unroll
            for (int i = 0; i < 4; i++) p4[i] = *(float4*)&Ps[(ty*4+i)*PS_LD + k4*4];
#pragma unroll
            for (int kk = 0; kk < 4; kk++) {
                float4 v0 = *(float4*)&Vs[(k4*4+kk)*128 + tx*8];
                float4 v1 = *(float4*)&Vs[(k4*4+kk)*128 + tx*8 + 4];
#pragma unroll
                for (int i = 0; i < 4; i++) {
                    float pv = (kk==0) ? p4[i].x : (kk==1) ? p4[i].y
                             : (kk==2) ? p4[i].z : p4[i].w;
                    acc[i][0] += pv*v0.x; acc[i][1] += pv*v0.y;
                    acc[i][2] += pv*v0.z; acc[i][3] += pv*v0.w;
                    acc[i][4] += pv*v1.x; acc[i][5] += pv*v1.y;
                    acc[i][6] += pv*v1.z; acc[i][7] += pv*v1.w;
                }
            }
        }
        __syncthreads();
    }

    // Epilogue: normalize and store to [b,s,h,d]
#pragma unroll
    for (int i = 0; i < 4; i++) {
        float inv = 1.0f / li[i];
        int r = m0 + ty*4 + i;
        float* op = O + (size_t)(b*S_ + r)*(NH_*D_) + h*D_ + tx*8;
        *(float4*)&op[0] = make_float4(acc[i][0]*inv, acc[i][1]*inv, acc[i][2]*inv, acc[i][3]*inv);
        *(float4*)&op[4] = make_float4(acc[i][4]*inv, acc[i][5]*inv, acc[i][6]*inv, acc[i][7]*inv);
    }
}

// ---------------------------------------------------------------------------
// kernel_launch
// inputs: 0 hidden_states, 1 cos, 2 sin, 3 attention_mask (unused, it is
// exactly causal and we apply causality analytically), 4 Wq, 5 Wk, 6 Wv, 7 Wo
// ---------------------------------------------------------------------------
extern "C" void kernel_launch(void* const* d_in, const int* in_sizes, int n_in,
                              void* d_out, int out_size)
{
    (void)in_sizes; (void)out_size;
    if (n_in < 8) return;
    const float* hs   = (const float*)d_in[0];
    const float* cosT = (const float*)d_in[1];
    const float* sinT = (const float*)d_in[2];
    const float* Wq   = (const float*)d_in[4];
    const float* Wk   = (const float*)d_in[5];
    const float* Wv   = (const float*)d_in[6];
    const float* Wo   = (const float*)d_in[7];
    float* out = (float*)d_out;

    float *QP, *KP, *VP, *AO;
    cudaGetSymbolAddress((void**)&QP, g_QP);
    cudaGetSymbolAddress((void**)&KP, g_KP);
    cudaGetSymbolAddress((void**)&VP, g_VP);
    cudaGetSymbolAddress((void**)&AO, g_AO);

    // Projections
    sgemm128<<<dim3(32,16), 256>>>(hs, Wq, QP, MROWS, NH_*D_,  H_);
    sgemm128<<<dim3(8, 16), 256>>>(hs, Wk, KP, MROWS, NKV_*D_, H_);
    sgemm128<<<dim3(8, 16), 256>>>(hs, Wv, VP, MROWS, NKV_*D_, H_);

    // RoPE (fold 1/sqrt(D) into Q)
    const float scale = 0.08838834764831845f;   // 128^-0.5
    rope_scale_kernel<<<(MROWS*NH_*64  + 255)/256, 256>>>(QP, cosT, sinT, NH_,  scale);
    rope_scale_kernel<<<(MROWS*NKV_*64 + 255)/256, 256>>>(KP, cosT, sinT, NKV_, 1.0f);

    // Flash attention
    int smem = FLASH_SMEM_FLOATS * (int)sizeof(float);   // ~115 KB
    cudaFuncSetAttribute(flash_kernel, cudaFuncAttributeMaxDynamicSharedMemorySize, smem);
    flash_kernel<<<dim3(S_/64, B_*NH_), 256, smem>>>(QP, KP, VP, AO);

    // Output projection
    sgemm128<<<dim3(32,16), 256>>>(AO, Wo, out, MROWS, H_, H_);
}

// round 11
// speedup vs baseline: 2.0850x; 2.0850x over previous
#include <cuda_runtime.h>
#include <cuda_bf16.h>
#include <math.h>
#include <stdint.h>

#define B_   2
#define S_   1024
#define H_   4096
#define NH_  32
#define NKV_ 8
#define D_   128
#define MROWS (B_*S_)   // 2048
#define KDIM 4096       // all GEMM K dims are 4096

// ------------------------- scratch (__device__ globals) --------------------
__device__ float g_QP[(size_t)MROWS*NH_*D_];
__device__ float g_KP[(size_t)MROWS*NKV_*D_];
__device__ float g_VP[(size_t)MROWS*NKV_*D_];
__device__ float g_AO[(size_t)MROWS*NH_*D_];

__device__ __nv_bfloat16 g_HShi[(size_t)MROWS*H_];
__device__ __nv_bfloat16 g_HSlo[(size_t)MROWS*H_];
__device__ __nv_bfloat16 g_AOhi[(size_t)MROWS*H_];
__device__ __nv_bfloat16 g_AOlo[(size_t)MROWS*H_];
__device__ __nv_bfloat16 g_WqThi[(size_t)H_*H_];        // [N, K] (K contiguous)
__device__ __nv_bfloat16 g_WqTlo[(size_t)H_*H_];
__device__ __nv_bfloat16 g_WkThi[(size_t)(NKV_*D_)*H_];
__device__ __nv_bfloat16 g_WkTlo[(size_t)(NKV_*D_)*H_];
__device__ __nv_bfloat16 g_WvThi[(size_t)(NKV_*D_)*H_];
__device__ __nv_bfloat16 g_WvTlo[(size_t)(NKV_*D_)*H_];
__device__ __nv_bfloat16 g_WoThi[(size_t)H_*H_];
__device__ __nv_bfloat16 g_WoTlo[(size_t)H_*H_];

// ------------------------- PTX helpers (base-target only) -------------------
__device__ __forceinline__ uint32_t smem_u32(const void* p) {
    uint32_t a;
    asm("{ .reg .u64 t; cvta.to.shared.u64 t, %1; cvt.u32.u64 %0, t; }"
        : "=r"(a) : "l"(p));
    return a;
}
__device__ __forceinline__ void cpasync16(uint32_t dst, const void* src) {
    asm volatile("cp.async.cg.shared.global [%0], [%1], 16;"
                 :: "r"(dst), "l"(src) : "memory");
}
#define CP_COMMIT()  asm volatile("cp.async.commit_group;" ::: "memory")
#define CP_WAIT(n)   asm volatile("cp.async.wait_group %0;" :: "n"(n) : "memory")

__device__ __forceinline__ void ldm4(uint32_t* r, uint32_t addr) {
    asm volatile("ldmatrix.sync.aligned.m8n8.x4.shared.b16 {%0,%1,%2,%3}, [%4];"
                 : "=r"(r[0]), "=r"(r[1]), "=r"(r[2]), "=r"(r[3]) : "r"(addr));
}
__device__ __forceinline__ void mma16816(float* d, const uint32_t* a,
                                         uint32_t b0, uint32_t b1) {
    asm volatile(
        "mma.sync.aligned.m16n8k16.row.col.f32.bf16.bf16.f32 "
        "{%0,%1,%2,%3}, {%4,%5,%6,%7}, {%8,%9}, {%0,%1,%2,%3};"
        : "+f"(d[0]), "+f"(d[1]), "+f"(d[2]), "+f"(d[3])
        : "r"(a[0]), "r"(a[1]), "r"(a[2]), "r"(a[3]), "r"(b0), "r"(b1));
}

// ------------------------- convert kernels ---------------------------------
__global__ void split_kernel(const float* __restrict__ X,
                             __nv_bfloat16* __restrict__ Hi,
                             __nv_bfloat16* __restrict__ Lo, int n)
{
    int i = blockIdx.x * blockDim.x + threadIdx.x;
    if (i >= n) return;
    float x = X[i];
    __nv_bfloat16 h = __float2bfloat16(x);
    Hi[i] = h;
    Lo[i] = __float2bfloat16(x - __bfloat162float(h));
}

// W [K,N] fp32 -> WT [N,K] bf16 hi/lo (tiled transpose)
__global__ void split_transpose_kernel(const float* __restrict__ W,
                                       __nv_bfloat16* __restrict__ Hi,
                                       __nv_bfloat16* __restrict__ Lo,
                                       int K, int N)
{
    __shared__ float tile[32][33];
    int n0 = blockIdx.x * 32, k0 = blockIdx.y * 32;
    int tx = threadIdx.x, ty = threadIdx.y;     // block (32,8)
#pragma unroll
    for (int i = 0; i < 4; i++)
        tile[ty + i*8][tx] = W[(size_t)(k0 + ty + i*8) * N + n0 + tx];
    __syncthreads();
#pragma unroll
    for (int i = 0; i < 4; i++) {
        float x = tile[tx][ty + i*8];
        __nv_bfloat16 h = __float2bfloat16(x);
        size_t o = (size_t)(n0 + ty + i*8) * K + k0 + tx;
        Hi[o] = h;
        Lo[o] = __float2bfloat16(x - __bfloat162float(h));
    }
}

// ------------------------- mma.sync split-bf16 GEMM -------------------------
// C[M,N] = A[M,K] @ B[K,N]; A as hi/lo bf16 [M,K]; B as BT hi/lo bf16 [N,K].
// CTA tile 128x128, k-chunk 32, 8 warps (2x4), warp tile 64x32.
// smem tile: 128 rows x 32 bf16 (64B rows), XOR swizzle c16 ^= (r>>1)&3.
#define TILE_BYTES 8192                  // 128 * 64B
#define STAGE_BYTES (4*TILE_BYTES)       // Ahi, Alo, Bhi, Blo
#define GEMM_SMEM (2*STAGE_BYTES)        // double buffer = 64 KB

__global__ __launch_bounds__(256) void gemm_mma(
    const __nv_bfloat16* __restrict__ Ahi, const __nv_bfloat16* __restrict__ Alo,
    const __nv_bfloat16* __restrict__ BThi, const __nv_bfloat16* __restrict__ BTlo,
    float* __restrict__ C, int N)
{
    extern __shared__ char smc[];
    const uint32_t smem0 = smem_u32(smc);
    const int t = threadIdx.x, lane = t & 31, warp = t >> 5;
    const int warp_m = warp >> 2, warp_n = warp & 3;
    const int bn0 = blockIdx.x * 128, bm0 = blockIdx.y * 128;

    const __nv_bfloat16* srcb[4] = {
        Ahi  + (size_t)bm0 * KDIM,  Alo  + (size_t)bm0 * KDIM,
        BThi + (size_t)bn0 * KDIM,  BTlo + (size_t)bn0 * KDIM };

    // per-thread cp.async decomposition: 2048 16B transfers, 8 per thread
    int ld_tile[8], ld_r[8], ld_c[8];
#pragma unroll
    for (int j = 0; j < 8; j++) {
        int g = t + j * 256;
        ld_tile[j] = g >> 9;
        int idx = g & 511;
        ld_r[j] = idx >> 2;
        ld_c[j] = idx & 3;
    }

    // ldmatrix per-lane offsets (chunk-invariant)
    uint32_t aoff[4][2], boff[2][2];
    {
        int aRow = warp_m * 64 + (lane & 15);
        int aKh  = lane >> 4;
#pragma unroll
        for (int mt = 0; mt < 4; mt++)
#pragma unroll
            for (int ks = 0; ks < 2; ks++) {
                int r = aRow + mt * 16;
                int logc = ks * 2 + aKh;
                aoff[mt][ks] = (uint32_t)(r * 64 + ((logc ^ ((r >> 1) & 3)) << 4));
            }
        int bRow = warp_n * 32 + ((lane >> 4) << 3) + (lane & 7);
        int bKh  = (lane >> 3) & 1;
#pragma unroll
        for (int np = 0; np < 2; np++)
#pragma unroll
            for (int ks = 0; ks < 2; ks++) {
                int r = bRow + np * 16;
                int logc = ks * 2 + bKh;
                boff[np][ks] = (uint32_t)(r * 64 + ((logc ^ ((r >> 1) & 3)) << 4));
            }
    }

    float acc[4][4][4];
#pragma unroll
    for (int mt = 0; mt < 4; mt++)
#pragma unroll
        for (int nt = 0; nt < 4; nt++)
#pragma unroll
            for (int k = 0; k < 4; k++) acc[mt][nt][k] = 0.f;

    auto issue_chunk = [&](int kt) {
        const int k0 = kt * 32;
        const uint32_t st = smem0 + (uint32_t)(kt & 1) * STAGE_BYTES;
#pragma unroll
        for (int j = 0; j < 8; j++) {
            const __nv_bfloat16* src =
                srcb[ld_tile[j]] + (size_t)ld_r[j] * KDIM + k0 + ld_c[j] * 8;
            uint32_t dst = st + (uint32_t)(ld_tile[j] * TILE_BYTES)
                         + (uint32_t)(ld_r[j] * 64)
                         + (uint32_t)((ld_c[j] ^ ((ld_r[j] >> 1) & 3)) << 4);
            cpasync16(dst, src);
        }
        CP_COMMIT();
    };

    const int nChunks = KDIM / 32;   // 128
    issue_chunk(0);

    for (int kt = 0; kt < nChunks; ++kt) {
        if (kt + 1 < nChunks) { issue_chunk(kt + 1); CP_WAIT(1); }
        else                  { CP_WAIT(0); }
        __syncthreads();

        const uint32_t st = smem0 + (uint32_t)(kt & 1) * STAGE_BYTES;
#pragma unroll
        for (int ks = 0; ks < 2; ks++) {
            uint32_t ah[4][4], al[4][4], bh[2][4], bl[2][4];
#pragma unroll
            for (int mt = 0; mt < 4; mt++) {
                ldm4(ah[mt], st + aoff[mt][ks]);
                ldm4(al[mt], st + TILE_BYTES + aoff[mt][ks]);
            }
#pragma unroll
            for (int np = 0; np < 2; np++) {
                ldm4(bh[np], st + 2*TILE_BYTES + boff[np][ks]);
                ldm4(bl[np], st + 3*TILE_BYTES + boff[np][ks]);
            }
#pragma unroll
            for (int mt = 0; mt < 4; mt++)
#pragma unroll
                for (int nt = 0; nt < 4; nt++) {
                    const int np = nt >> 1, ro = (nt & 1) * 2;
                    mma16816(acc[mt][nt], ah[mt], bh[np][ro], bh[np][ro+1]);
                    mma16816(acc[mt][nt], ah[mt], bl[np][ro], bl[np][ro+1]);
                    mma16816(acc[mt][nt], al[mt], bh[np][ro], bh[np][ro+1]);
                }
        }
        __syncthreads();
    }

    // epilogue
    const int gid = lane >> 2, tig = lane & 3;
#pragma unroll
    for (int mt = 0; mt < 4; mt++) {
        const int row = bm0 + warp_m * 64 + mt * 16 + gid;
#pragma unroll
        for (int nt = 0; nt < 4; nt++) {
            const int col = bn0 + warp_n * 32 + nt * 8 + tig * 2;
            *(float2*)&C[(size_t)row * N + col] =
                make_float2(acc[mt][nt][0], acc[mt][nt][1]);
            *(float2*)&C[(size_t)(row + 8) * N + col] =
                make_float2(acc[mt][nt][2], acc[mt][nt][3]);
        }
    }
}

// ------------------------- RoPE --------------------------------------------
__global__ void rope_scale_kernel(float* __restrict__ X,
                                  const float* __restrict__ cosT,
                                  const float* __restrict__ sinT,
                                  int nheads, float scale)
{
    int idx = blockIdx.x * blockDim.x + threadIdx.x;
    int total = MROWS * nheads * (D_/2);
    if (idx >= total) return;
    int d    = idx & 63;
    int rest = idx >> 6;
    int h = rest % nheads;
    int m = rest / nheads;
    float* p = X + ((size_t)m * nheads + h) * D_;
    float q1 = p[d], q2 = p[d+64];
    float c1 = cosT[m*D_ + d],      s1 = sinT[m*D_ + d];
    float c2 = cosT[m*D_ + d + 64], s2 = sinT[m*D_ + d + 64];
    p[d]    = (q1*c1 - q2*s1) * scale;
    p[d+64] = (q2*c2 + q1*s2) * scale;
}

// ------------------------- flash attention (fp32, proven) -------------------
#define QS_LD 132
#define KS_LD 132
#define PS_LD 68
#define FLASH_SMEM_FLOATS (64*QS_LD + 64*KS_LD + 64*128 + 64*PS_LD)

__global__ __launch_bounds__(256) void flash_kernel(
    const float* __restrict__ Q, const float* __restrict__ K,
    const float* __restrict__ V, float* __restrict__ O)
{
    extern __shared__ float smf[];
    float* Qs = smf;
    float* Ks = Qs + 64*QS_LD;
    float* Vs = Ks + 64*KS_LD;
    float* Ps = Vs + 64*128;

    const int t  = threadIdx.x;
    const int tx = t & 15, ty = t >> 4;
    const int m0 = blockIdx.x * 64;
    const int bh = blockIdx.y;
    const int b  = bh >> 5;
    const int h  = bh & 31;
    const int kvh = h >> 2;

    const float* Qb = Q + (size_t)b*S_*NH_*D_  + h*D_;
    const float* Kb = K + (size_t)b*S_*NKV_*D_ + kvh*D_;
    const float* Vb = V + (size_t)b*S_*NKV_*D_ + kvh*D_;

    for (int l = t; l < 64*32; l += 256) {
        int r = l >> 5, c4 = (l & 31) * 4;
        *(float4*)&Qs[r*QS_LD + c4] = *(const float4*)(Qb + (size_t)(m0 + r)*(NH_*D_) + c4);
    }

    float acc[4][8];
#pragma unroll
    for (int i = 0; i < 4; i++)
#pragma unroll
        for (int j = 0; j < 8; j++) acc[i][j] = 0.f;
    float mi[4] = {-1e30f,-1e30f,-1e30f,-1e30f};
    float li[4] = {0.f,0.f,0.f,0.f};

    const int nT = blockIdx.x + 1;
    for (int itt = 0; itt < nT; ++itt) {
        int n0 = itt * 64;
        for (int l = t; l < 64*32; l += 256) {
            int r = l >> 5, c4 = (l & 31) * 4;
            *(float4*)&Ks[r*KS_LD + c4] = *(const float4*)(Kb + (size_t)(n0 + r)*(NKV_*D_) + c4);
            *(float4*)&Vs[r*128 + c4]   = *(const float4*)(Vb + (size_t)(n0 + r)*(NKV_*D_) + c4);
        }
        __syncthreads();

        float s[4][4];
#pragma unroll
        for (int i = 0; i < 4; i++)
#pragma unroll
            for (int j = 0; j < 4; j++) s[i][j] = 0.f;
        for (int k4 = 0; k4 < 32; k4++) {
            float4 qa[4], kb[4];
#pragma unroll
            for (int i = 0; i < 4; i++) qa[i] = *(float4*)&Qs[(ty*4+i)*QS_LD + k4*4];
#pragma unroll
            for (int j = 0; j < 4; j++) kb[j] = *(float4*)&Ks[(tx*4+j)*KS_LD + k4*4];
#pragma unroll
            for (int i = 0; i < 4; i++)
#pragma unroll
                for (int j = 0; j < 4; j++)
                    s[i][j] += qa[i].x*kb[j].x + qa[i].y*kb[j].y
                             + qa[i].z*kb[j].z + qa[i].w*kb[j].w;
        }
        if (n0 == m0) {
#pragma unroll
            for (int i = 0; i < 4; i++)
#pragma unroll
                for (int j = 0; j < 4; j++)
                    if (tx*4 + j > ty*4 + i) s[i][j] = -1e30f;
        }

#pragma unroll
        for (int i = 0; i < 4; i++) {
            float ml = fmaxf(fmaxf(s[i][0], s[i][1]), fmaxf(s[i][2], s[i][3]));
#pragma unroll
            for (int off = 8; off > 0; off >>= 1)
                ml = fmaxf(ml, __shfl_xor_sync(0xffffffffu, ml, off));
            float mnew  = fmaxf(mi[i], ml);
            float alpha = __expf(mi[i] - mnew);
            mi[i] = mnew;
            float4 pr;
            pr.x = __expf(s[i][0] - mnew); pr.y = __expf(s[i][1] - mnew);
            pr.z = __expf(s[i][2] - mnew); pr.w = __expf(s[i][3] - mnew);
            float rsum = pr.x + pr.y + pr.z + pr.w;
            *(float4*)&Ps[(ty*4+i)*PS_LD + tx*4] = pr;
#pragma unroll
            for (int off = 8; off > 0; off >>= 1)
                rsum += __shfl_xor_sync(0xffffffffu, rsum, off);
            li[i] = li[i]*alpha + rsum;
#pragma unroll
            for (int j = 0; j < 8; j++) acc[i][j] *= alpha;
        }
        __syncthreads();

        for (int k4 = 0; k4 < 16; k4++) {
            float4 p4[4];
#pragma unroll
            for (int i = 0; i < 4; i++) p4[i] = *(float4*)&Ps[(ty*4+i)*PS_LD + k4*4];
#pragma unroll
            for (int kk = 0; kk < 4; kk++) {
                float4 v0 = *(float4*)&Vs[(k4*4+kk)*128 + tx*8];
                float4 v1 = *(float4*)&Vs[(k4*4+kk)*128 + tx*8 + 4];
#pragma unroll
                for (int i = 0; i < 4; i++) {
                    float pv = (kk==0) ? p4[i].x : (kk==1) ? p4[i].y
                             : (kk==2) ? p4[i].z : p4[i].w;
                    acc[i][0] += pv*v0.x; acc[i][1] += pv*v0.y;
                    acc[i][2] += pv*v0.z; acc[i][3] += pv*v0.w;
                    acc[i][4] += pv*v1.x; acc[i][5] += pv*v1.y;
                    acc[i][6] += pv*v1.z; acc[i][7] += pv*v1.w;
                }
            }
        }
        __syncthreads();
    }

#pragma unroll
    for (int i = 0; i < 4; i++) {
        float inv = 1.0f / li[i];
        int r = m0 + ty*4 + i;
        float* op = O + (size_t)(b*S_ + r)*(NH_*D_) + h*D_ + tx*8;
        *(float4*)&op[0] = make_float4(acc[i][0]*inv, acc[i][1]*inv, acc[i][2]*inv, acc[i][3]*inv);
        *(float4*)&op[4] = make_float4(acc[i][4]*inv, acc[i][5]*inv, acc[i][6]*inv, acc[i][7]*inv);
    }
}

// ------------------------- kernel_launch -----------------------------------
// inputs: 0 hidden_states, 1 cos, 2 sin, 3 attention_mask (causal, applied
// analytically), 4 Wq, 5 Wk, 6 Wv, 7 Wo
extern "C" void kernel_launch(void* const* d_in, const int* in_sizes, int n_in,
                              void* d_out, int out_size)
{
    (void)in_sizes; (void)out_size;
    if (n_in < 8) return;
    const float* hs   = (const float*)d_in[0];
    const float* cosT = (const float*)d_in[1];
    const float* sinT = (const float*)d_in[2];
    const float* Wq   = (const float*)d_in[4];
    const float* Wk   = (const float*)d_in[5];
    const float* Wv   = (const float*)d_in[6];
    const float* Wo   = (const float*)d_in[7];
    float* out = (float*)d_out;

    float *QP, *KP, *VP, *AO;
    cudaGetSymbolAddress((void**)&QP, g_QP);
    cudaGetSymbolAddress((void**)&KP, g_KP);
    cudaGetSymbolAddress((void**)&VP, g_VP);
    cudaGetSymbolAddress((void**)&AO, g_AO);
    __nv_bfloat16 *HShi, *HSlo, *AOhi, *AOlo;
    __nv_bfloat16 *WqThi, *WqTlo, *WkThi, *WkTlo, *WvThi, *WvTlo, *WoThi, *WoTlo;
    cudaGetSymbolAddress((void**)&HShi, g_HShi);
    cudaGetSymbolAddress((void**)&HSlo, g_HSlo);
    cudaGetSymbolAddress((void**)&AOhi, g_AOhi);
    cudaGetSymbolAddress((void**)&AOlo, g_AOlo);
    cudaGetSymbolAddress((void**)&WqThi, g_WqThi);
    cudaGetSymbolAddress((void**)&WqTlo, g_WqTlo);
    cudaGetSymbolAddress((void**)&WkThi, g_WkThi);
    cudaGetSymbolAddress((void**)&WkTlo, g_WkTlo);
    cudaGetSymbolAddress((void**)&WvThi, g_WvThi);
    cudaGetSymbolAddress((void**)&WvTlo, g_WvTlo);
    cudaGetSymbolAddress((void**)&WoThi, g_WoThi);
    cudaGetSymbolAddress((void**)&WoTlo, g_WoTlo);

    // 1) split conversions
    {
        int n = MROWS * H_;
        split_kernel<<<(n + 255)/256, 256>>>(hs, HShi, HSlo, n);
    }
    split_transpose_kernel<<<dim3(H_/32, H_/32),        dim3(32,8)>>>(Wq, WqThi, WqTlo, H_, H_);
    split_transpose_kernel<<<dim3((NKV_*D_)/32, H_/32), dim3(32,8)>>>(Wk, WkThi, WkTlo, H_, NKV_*D_);
    split_transpose_kernel<<<dim3((NKV_*D_)/32, H_/32), dim3(32,8)>>>(Wv, WvThi, WvTlo, H_, NKV_*D_);
    split_transpose_kernel<<<dim3(H_/32, H_/32),        dim3(32,8)>>>(Wo, WoThi, WoTlo, H_, H_);

    // 2) projections on tensor cores (mma.sync split-bf16)
    cudaFuncSetAttribute(gemm_mma, cudaFuncAttributeMaxDynamicSharedMemorySize, GEMM_SMEM);
    gemm_mma<<<dim3((NH_*D_)/128,  MROWS/128), 256, GEMM_SMEM>>>(HShi, HSlo, WqThi, WqTlo, QP, NH_*D_);
    gemm_mma<<<dim3((NKV_*D_)/128, MROWS/128), 256, GEMM_SMEM>>>(HShi, HSlo, WkThi, WkTlo, KP, NKV_*D_);
    gemm_mma<<<dim3((NKV_*D_)/128, MROWS/128), 256, GEMM_SMEM>>>(HShi, HSlo, WvThi, WvTlo, VP, NKV_*D_);

    // 3) RoPE (fold 1/sqrt(D) into Q)
    const float scale = 0.08838834764831845f;
    rope_scale_kernel<<<(MROWS*NH_*64  + 255)/256, 256>>>(QP, cosT, sinT, NH_,  scale);
    rope_scale_kernel<<<(MROWS*NKV_*64 + 255)/256, 256>>>(KP, cosT, sinT, NKV_, 1.0f);

    // 4) flash attention (fp32)
    int smemf = FLASH_SMEM_FLOATS * (int)sizeof(float);
    cudaFuncSetAttribute(flash_kernel, cudaFuncAttributeMaxDynamicSharedMemorySize, smemf);
    flash_kernel<<<dim3(S_/64, B_*NH_), 256, smemf>>>(QP, KP, VP, AO);

    // 5) output projection
    {
        int n = MROWS * H_;
        split_kernel<<<(n + 255)/256, 256>>>(AO, AOhi, AOlo, n);
    }
    gemm_mma<<<dim3(H_/128, MROWS/128), 256, GEMM_SMEM>>>(AOhi, AOlo, WoThi, WoTlo, out, H_);
}

// round 13
// speedup vs baseline: 2.0865x; 1.0007x over previous
#include <cuda_runtime.h>
#include <cuda_bf16.h>
#include <math.h>
#include <stdint.h>

#define B_   2
#define S_   1024
#define H_   4096
#define NH_  32
#define NKV_ 8
#define D_   128
#define MROWS (B_*S_)   // 2048
#define KDIM 4096       // all GEMM K dims are 4096

// ------------------------- scratch (__device__ globals) --------------------
__device__ float g_QP[(size_t)MROWS*NH_*D_];
__device__ float g_KP[(size_t)MROWS*NKV_*D_];
__device__ float g_VP[(size_t)MROWS*NKV_*D_];
__device__ float g_AO[(size_t)MROWS*NH_*D_];

__device__ __nv_bfloat16 g_HShi[(size_t)MROWS*H_];
__device__ __nv_bfloat16 g_HSlo[(size_t)MROWS*H_];
__device__ __nv_bfloat16 g_AOhi[(size_t)MROWS*H_];
__device__ __nv_bfloat16 g_AOlo[(size_t)MROWS*H_];
__device__ __nv_bfloat16 g_WqThi[(size_t)H_*H_];        // [N, K] (K contiguous)
__device__ __nv_bfloat16 g_WqTlo[(size_t)H_*H_];
__device__ __nv_bfloat16 g_WkThi[(size_t)(NKV_*D_)*H_];
__device__ __nv_bfloat16 g_WkTlo[(size_t)(NKV_*D_)*H_];
__device__ __nv_bfloat16 g_WvThi[(size_t)(NKV_*D_)*H_];
__device__ __nv_bfloat16 g_WvTlo[(size_t)(NKV_*D_)*H_];
__device__ __nv_bfloat16 g_WoThi[(size_t)H_*H_];
__device__ __nv_bfloat16 g_WoTlo[(size_t)H_*H_];

// ------------------------- PTX helpers (base-target only) -------------------
__device__ __forceinline__ uint32_t smem_u32(const void* p) {
    uint32_t a;
    asm("{ .reg .u64 t; cvta.to.shared.u64 t, %1; cvt.u32.u64 %0, t; }"
        : "=r"(a) : "l"(p));
    return a;
}
__device__ __forceinline__ void cpasync16(uint32_t dst, const void* src) {
    asm volatile("cp.async.cg.shared.global [%0], [%1], 16;"
                 :: "r"(dst), "l"(src) : "memory");
}
#define CP_COMMIT()  asm volatile("cp.async.commit_group;" ::: "memory")
#define CP_WAIT(n)   asm volatile("cp.async.wait_group %0;" :: "n"(n) : "memory")

__device__ __forceinline__ void ldm4(uint32_t* r, uint32_t addr) {
    asm volatile("ldmatrix.sync.aligned.m8n8.x4.shared.b16 {%0,%1,%2,%3}, [%4];"
                 : "=r"(r[0]), "=r"(r[1]), "=r"(r[2]), "=r"(r[3]) : "r"(addr));
}
__device__ __forceinline__ void mma16816(float* d, const uint32_t* a,
                                         uint32_t b0, uint32_t b1) {
    asm volatile(
        "mma.sync.aligned.m16n8k16.row.col.f32.bf16.bf16.f32 "
        "{%0,%1,%2,%3}, {%4,%5,%6,%7}, {%8,%9}, {%0,%1,%2,%3};"
        : "+f"(d[0]), "+f"(d[1]), "+f"(d[2]), "+f"(d[3])
        : "r"(a[0]), "r"(a[1]), "r"(a[2]), "r"(a[3]), "r"(b0), "r"(b1));
}

// ------------------------- convert kernels ---------------------------------
__global__ void split_kernel(const float* __restrict__ X,
                             __nv_bfloat16* __restrict__ Hi,
                             __nv_bfloat16* __restrict__ Lo, int n)
{
    int i = blockIdx.x * blockDim.x + threadIdx.x;
    if (i >= n) return;
    float x = X[i];
    __nv_bfloat16 h = __float2bfloat16(x);
    Hi[i] = h;
    Lo[i] = __float2bfloat16(x - __bfloat162float(h));
}

// W [K,N] fp32 -> WT [N,K] bf16 hi/lo (tiled transpose)
__global__ void split_transpose_kernel(const float* __restrict__ W,
                                       __nv_bfloat16* __restrict__ Hi,
                                       __nv_bfloat16* __restrict__ Lo,
                                       int K, int N)
{
    __shared__ float tile[32][33];
    int n0 = blockIdx.x * 32, k0 = blockIdx.y * 32;
    int tx = threadIdx.x, ty = threadIdx.y;     // block (32,8)
#pragma unroll
    for (int i = 0; i < 4; i++)
        tile[ty + i*8][tx] = W[(size_t)(k0 + ty + i*8) * N + n0 + tx];
    __syncthreads();
#pragma unroll
    for (int i = 0; i < 4; i++) {
        float x = tile[tx][ty + i*8];
        __nv_bfloat16 h = __float2bfloat16(x);
        size_t o = (size_t)(n0 + ty + i*8) * K + k0 + tx;
        Hi[o] = h;
        Lo[o] = __float2bfloat16(x - __bfloat162float(h));
    }
}

// ------------------------- mma.sync split-bf16 GEMM -------------------------
// C[M,N] = A[M,K] @ B[K,N]; A as hi/lo bf16 [M,K]; B as BT hi/lo bf16 [N,K].
// CTA tile 128x128, k-chunk 32, 8 warps (2x4), warp tile 64x32.
// smem tile: 128 rows x 32 bf16 (64B rows), XOR swizzle c16 ^= (r>>1)&3.
#define TILE_BYTES 8192                  // 128 * 64B
#define STAGE_BYTES (4*TILE_BYTES)       // Ahi, Alo, Bhi, Blo
#define GEMM_SMEM (2*STAGE_BYTES)        // double buffer = 64 KB

__global__ __launch_bounds__(256) void gemm_mma(
    const __nv_bfloat16* __restrict__ Ahi, const __nv_bfloat16* __restrict__ Alo,
    const __nv_bfloat16* __restrict__ BThi, const __nv_bfloat16* __restrict__ BTlo,
    float* __restrict__ C, int N)
{
    extern __shared__ char smc[];
    const uint32_t smem0 = smem_u32(smc);
    const int t = threadIdx.x, lane = t & 31, warp = t >> 5;
    const int warp_m = warp >> 2, warp_n = warp & 3;
    const int bn0 = blockIdx.x * 128, bm0 = blockIdx.y * 128;

    const __nv_bfloat16* srcb[4] = {
        Ahi  + (size_t)bm0 * KDIM,  Alo  + (size_t)bm0 * KDIM,
        BThi + (size_t)bn0 * KDIM,  BTlo + (size_t)bn0 * KDIM };

    // per-thread cp.async decomposition: 2048 16B transfers, 8 per thread
    int ld_tile[8], ld_r[8], ld_c[8];
#pragma unroll
    for (int j = 0; j < 8; j++) {
        int g = t + j * 256;
        ld_tile[j] = g >> 9;
        int idx = g & 511;
        ld_r[j] = idx >> 2;
        ld_c[j] = idx & 3;
    }

    // ldmatrix per-lane offsets (chunk-invariant)
    uint32_t aoff[4][2], boff[2][2];
    {
        int aRow = warp_m * 64 + (lane & 15);
        int aKh  = lane >> 4;
#pragma unroll
        for (int mt = 0; mt < 4; mt++)
#pragma unroll
            for (int ks = 0; ks < 2; ks++) {
                int r = aRow + mt * 16;
                int logc = ks * 2 + aKh;
                aoff[mt][ks] = (uint32_t)(r * 64 + ((logc ^ ((r >> 1) & 3)) << 4));
            }
        int bRow = warp_n * 32 + ((lane >> 4) << 3) + (lane & 7);
        int bKh  = (lane >> 3) & 1;
#pragma unroll
        for (int np = 0; np < 2; np++)
#pragma unroll
            for (int ks = 0; ks < 2; ks++) {
                int r = bRow + np * 16;
                int logc = ks * 2 + bKh;
                boff[np][ks] = (uint32_t)(r * 64 + ((logc ^ ((r >> 1) & 3)) << 4));
            }
    }

    float acc[4][4][4];
#pragma unroll
    for (int mt = 0; mt < 4; mt++)
#pragma unroll
        for (int nt = 0; nt < 4; nt++)
#pragma unroll
            for (int k = 0; k < 4; k++) acc[mt][nt][k] = 0.f;

    auto issue_chunk = [&](int kt) {
        const int k0 = kt * 32;
        const uint32_t st = smem0 + (uint32_t)(kt & 1) * STAGE_BYTES;
#pragma unroll
        for (int j = 0; j < 8; j++) {
            const __nv_bfloat16* src =
                srcb[ld_tile[j]] + (size_t)ld_r[j] * KDIM + k0 + ld_c[j] * 8;
            uint32_t dst = st + (uint32_t)(ld_tile[j] * TILE_BYTES)
                         + (uint32_t)(ld_r[j] * 64)
                         + (uint32_t)((ld_c[j] ^ ((ld_r[j] >> 1) & 3)) << 4);
            cpasync16(dst, src);
        }
        CP_COMMIT();
    };

    const int nChunks = KDIM / 32;   // 128
    issue_chunk(0);

    for (int kt = 0; kt < nChunks; ++kt) {
        if (kt + 1 < nChunks) { issue_chunk(kt + 1); CP_WAIT(1); }
        else                  { CP_WAIT(0); }
        __syncthreads();

        const uint32_t st = smem0 + (uint32_t)(kt & 1) * STAGE_BYTES;
#pragma unroll
        for (int ks = 0; ks < 2; ks++) {
            uint32_t ah[4][4], al[4][4], bh[2][4], bl[2][4];
#pragma unroll
            for (int mt = 0; mt < 4; mt++) {
                ldm4(ah[mt], st + aoff[mt][ks]);
                ldm4(al[mt], st + TILE_BYTES + aoff[mt][ks]);
            }
#pragma unroll
            for (int np = 0; np < 2; np++) {
                ldm4(bh[np], st + 2*TILE_BYTES + boff[np][ks]);
                ldm4(bl[np], st + 3*TILE_BYTES + boff[np][ks]);
            }
#pragma unroll
            for (int mt = 0; mt < 4; mt++)
#pragma unroll
                for (int nt = 0; nt < 4; nt++) {
                    const int np = nt >> 1, ro = (nt & 1) * 2;
                    mma16816(acc[mt][nt], ah[mt], bh[np][ro], bh[np][ro+1]);
                    mma16816(acc[mt][nt], ah[mt], bl[np][ro], bl[np][ro+1]);
                    mma16816(acc[mt][nt], al[mt], bh[np][ro], bh[np][ro+1]);
                }
        }
        __syncthreads();
    }

    // epilogue
    const int gid = lane >> 2, tig = lane & 3;
#pragma unroll
    for (int mt = 0; mt < 4; mt++) {
        const int row = bm0 + warp_m * 64 + mt * 16 + gid;
#pragma unroll
        for (int nt = 0; nt < 4; nt++) {
            const int col = bn0 + warp_n * 32 + nt * 8 + tig * 2;
            *(float2*)&C[(size_t)row * N + col] =
                make_float2(acc[mt][nt][0], acc[mt][nt][1]);
            *(float2*)&C[(size_t)(row + 8) * N + col] =
                make_float2(acc[mt][nt][2], acc[mt][nt][3]);
        }
    }
}

// ------------------------- RoPE --------------------------------------------
__global__ void rope_scale_kernel(float* __restrict__ X,
                                  const float* __restrict__ cosT,
                                  const float* __restrict__ sinT,
                                  int nheads, float scale)
{
    int idx = blockIdx.x * blockDim.x + threadIdx.x;
    int total = MROWS * nheads * (D_/2);
    if (idx >= total) return;
    int d    = idx & 63;
    int rest = idx >> 6;
    int h = rest % nheads;
    int m = rest / nheads;
    float* p = X + ((size_t)m * nheads + h) * D_;
    float q1 = p[d], q2 = p[d+64];
    float c1 = cosT[m*D_ + d],      s1 = sinT[m*D_ + d];
    float c2 = cosT[m*D_ + d + 64], s2 = sinT[m*D_ + d + 64];
    p[d]    = (q1*c1 - q2*s1) * scale;
    p[d+64] = (q2*c2 + q1*s2) * scale;
}

// ------------------------- flash attention (fp32, proven) -------------------
#define QS_LD 132
#define KS_LD 132
#define PS_LD 68
#define FLASH_SMEM_FLOATS (64*QS_LD + 64*KS_LD + 64*128 + 64*PS_LD)

__global__ __launch_bounds__(256) void flash_kernel(
    const float* __restrict__ Q, const float* __restrict__ K,
    const float* __restrict__ V, float* __restrict__ O)
{
    extern __shared__ float smf[];
    float* Qs = smf;
    float* Ks = Qs + 64*QS_LD;
    float* Vs = Ks + 64*KS_LD;
    float* Ps = Vs + 64*128;

    const int t  = threadIdx.x;
    const int tx = t & 15, ty = t >> 4;
    const int m0 = blockIdx.x * 64;
    const int bh = blockIdx.y;
    const int b  = bh >> 5;
    const int h  = bh & 31;
    const int kvh = h >> 2;

    const float* Qb = Q + (size_t)b*S_*NH_*D_  + h*D_;
    const float* Kb = K + (size_t)b*S_*NKV_*D_ + kvh*D_;
    const float* Vb = V + (size_t)b*S_*NKV_*D_ + kvh*D_;

    for (int l = t; l < 64*32; l += 256) {
        int r = l >> 5, c4 = (l & 31) * 4;
        *(float4*)&Qs[r*QS_LD + c4] = *(const float4*)(Qb + (size_t)(m0 + r)*(NH_*D_) + c4);
    }

    float acc[4][8];
#pragma unroll
    for (int i = 0; i < 4; i++)
#pragma unroll
        for (int j = 0; j < 8; j++) acc[i][j] = 0.f;
    float mi[4] = {-1e30f,-1e30f,-1e30f,-1e30f};
    float li[4] = {0.f,0.f,0.f,0.f};

    const int nT = blockIdx.x + 1;
    for (int itt = 0; itt < nT; ++itt) {
        int n0 = itt * 64;
        for (int l = t; l < 64*32; l += 256) {
            int r = l >> 5, c4 = (l & 31) * 4;
            *(float4*)&Ks[r*KS_LD + c4] = *(const float4*)(Kb + (size_t)(n0 + r)*(NKV_*D_) + c4);
            *(float4*)&Vs[r*128 + c4]   = *(const float4*)(Vb + (size_t)(n0 + r)*(NKV_*D_) + c4);
        }
        __syncthreads();

        float s[4][4];
#pragma unroll
        for (int i = 0; i < 4; i++)
#pragma unroll
            for (int j = 0; j < 4; j++) s[i][j] = 0.f;
        for (int k4 = 0; k4 < 32; k4++) {
            float4 qa[4], kb[4];
#pragma unroll
            for (int i = 0; i < 4; i++) qa[i] = *(float4*)&Qs[(ty*4+i)*QS_LD + k4*4];
#pragma unroll
            for (int j = 0; j < 4; j++) kb[j] = *(float4*)&Ks[(tx*4+j)*KS_LD + k4*4];
#pragma unroll
            for (int i = 0; i < 4; i++)
#pragma unroll
                for (int j = 0; j < 4; j++)
                    s[i][j] += qa[i].x*kb[j].x + qa[i].y*kb[j].y
                             + qa[i].z*kb[j].z + qa[i].w*kb[j].w;
        }
        if (n0 == m0) {
#pragma unroll
            for (int i = 0; i < 4; i++)
#pragma unroll
                for (int j = 0; j < 4; j++)
                    if (tx*4 + j > ty*4 + i) s[i][j] = -1e30f;
        }

#pragma unroll
        for (int i = 0; i < 4; i++) {
            float ml = fmaxf(fmaxf(s[i][0], s[i][1]), fmaxf(s[i][2], s[i][3]));
#pragma unroll
            for (int off = 8; off > 0; off >>= 1)
                ml = fmaxf(ml, __shfl_xor_sync(0xffffffffu, ml, off));
            float mnew  = fmaxf(mi[i], ml);
            float alpha = __expf(mi[i] - mnew);
            mi[i] = mnew;
            float4 pr;
            pr.x = __expf(s[i][0] - mnew); pr.y = __expf(s[i][1] - mnew);
            pr.z = __expf(s[i][2] - mnew); pr.w = __expf(s[i][3] - mnew);
            float rsum = pr.x + pr.y + pr.z + pr.w;
            *(float4*)&Ps[(ty*4+i)*PS_LD + tx*4] = pr;
#pragma unroll
            for (int off = 8; off > 0; off >>= 1)
                rsum += __shfl_xor_sync(0xffffffffu, rsum, off);
            li[i] = li[i]*alpha + rsum;
#pragma unroll
            for (int j = 0; j < 8; j++) acc[i][j] *= alpha;
        }
        __syncthreads();

        for (int k4 = 0; k4 < 16; k4++) {
            float4 p4[4];
#pragma unroll
            for (int i = 0; i < 4; i++) p4[i] = *(float4*)&Ps[(ty*4+i)*PS_LD + k4*4];
#pragma unroll
            for (int kk = 0; kk < 4; kk++) {
                float4 v0 = *(float4*)&Vs[(k4*4+kk)*128 + tx*8];
                float4 v1 = *(float4*)&Vs[(k4*4+kk)*128 + tx*8 + 4];
#pragma unroll
                for (int i = 0; i < 4; i++) {
                    float pv = (kk==0) ? p4[i].x : (kk==1) ? p4[i].y
                             : (kk==2) ? p4[i].z : p4[i].w;
                    acc[i][0] += pv*v0.x; acc[i][1] += pv*v0.y;
                    acc[i][2] += pv*v0.z; acc[i][3] += pv*v0.w;
                    acc[i][4] += pv*v1.x; acc[i][5] += pv*v1.y;
                    acc[i][6] += pv*v1.z; acc[i][7] += pv*v1.w;
                }
            }
        }
        __syncthreads();
    }

#pragma unroll
    for (int i = 0; i < 4; i++) {
        float inv = 1.0f / li[i];
        int r = m0 + ty*4 + i;
        float* op = O + (size_t)(b*S_ + r)*(NH_*D_) + h*D_ + tx*8;
        *(float4*)&op[0] = make_float4(acc[i][0]*inv, acc[i][1]*inv, acc[i][2]*inv, acc[i][3]*inv);
        *(float4*)&op[4] = make_float4(acc[i][4]*inv, acc[i][5]*inv, acc[i][6]*inv, acc[i][7]*inv);
    }
}

// ------------------------- kernel_launch -----------------------------------
// inputs: 0 hidden_states, 1 cos, 2 sin, 3 attention_mask (causal, applied
// analytically), 4 Wq, 5 Wk, 6 Wv, 7 Wo
extern "C" void kernel_launch(void* const* d_in, const int* in_sizes, int n_in,
                              void* d_out, int out_size)
{
    (void)in_sizes; (void)out_size;
    if (n_in < 8) return;
    const float* hs   = (const float*)d_in[0];
    const float* cosT = (const float*)d_in[1];
    const float* sinT = (const float*)d_in[2];
    const float* Wq   = (const float*)d_in[4];
    const float* Wk   = (const float*)d_in[5];
    const float* Wv   = (const float*)d_in[6];
    const float* Wo   = (const float*)d_in[7];
    float* out = (float*)d_out;

    float *QP, *KP, *VP, *AO;
    cudaGetSymbolAddress((void**)&QP, g_QP);
    cudaGetSymbolAddress((void**)&KP, g_KP);
    cudaGetSymbolAddress((void**)&VP, g_VP);
    cudaGetSymbolAddress((void**)&AO, g_AO);
    __nv_bfloat16 *HShi, *HSlo, *AOhi, *AOlo;
    __nv_bfloat16 *WqThi, *WqTlo, *WkThi, *WkTlo, *WvThi, *WvTlo, *WoThi, *WoTlo;
    cudaGetSymbolAddress((void**)&HShi, g_HShi);
    cudaGetSymbolAddress((void**)&HSlo, g_HSlo);
    cudaGetSymbolAddress((void**)&AOhi, g_AOhi);
    cudaGetSymbolAddress((void**)&AOlo, g_AOlo);
    cudaGetSymbolAddress((void**)&WqThi, g_WqThi);
    cudaGetSymbolAddress((void**)&WqTlo, g_WqTlo);
    cudaGetSymbolAddress((void**)&WkThi, g_WkThi);
    cudaGetSymbolAddress((void**)&WkTlo, g_WkTlo);
    cudaGetSymbolAddress((void**)&WvThi, g_WvThi);
    cudaGetSymbolAddress((void**)&WvTlo, g_WvTlo);
    cudaGetSymbolAddress((void**)&WoThi, g_WoThi);
    cudaGetSymbolAddress((void**)&WoTlo, g_WoTlo);

    // 1) split conversions
    {
        int n = MROWS * H_;
        split_kernel<<<(n + 255)/256, 256>>>(hs, HShi, HSlo, n);
    }
    split_transpose_kernel<<<dim3(H_/32, H_/32),        dim3(32,8)>>>(Wq, WqThi, WqTlo, H_, H_);
    split_transpose_kernel<<<dim3((NKV_*D_)/32, H_/32), dim3(32,8)>>>(Wk, WkThi, WkTlo, H_, NKV_*D_);
    split_transpose_kernel<<<dim3((NKV_*D_)/32, H_/32), dim3(32,8)>>>(Wv, WvThi, WvTlo, H_, NKV_*D_);
    split_transpose_kernel<<<dim3(H_/32, H_/32),        dim3(32,8)>>>(Wo, WoThi, WoTlo, H_, H_);

    // 2) projections on tensor cores (mma.sync split-bf16)
    cudaFuncSetAttribute(gemm_mma, cudaFuncAttributeMaxDynamicSharedMemorySize, GEMM_SMEM);
    gemm_mma<<<dim3((NH_*D_)/128,  MROWS/128), 256, GEMM_SMEM>>>(HShi, HSlo, WqThi, WqTlo, QP, NH_*D_);
    gemm_mma<<<dim3((NKV_*D_)/128, MROWS/128), 256, GEMM_SMEM>>>(HShi, HSlo, WkThi, WkTlo, KP, NKV_*D_);
    gemm_mma<<<dim3((NKV_*D_)/128, MROWS/128), 256, GEMM_SMEM>>>(HShi, HSlo, WvThi, WvTlo, VP, NKV_*D_);

    // 3) RoPE (fold 1/sqrt(D) into Q)
    const float scale = 0.08838834764831845f;
    rope_scale_kernel<<<(MROWS*NH_*64  + 255)/256, 256>>>(QP, cosT, sinT, NH_,  scale);
    rope_scale_kernel<<<(MROWS*NKV_*64 + 255)/256, 256>>>(KP, cosT, sinT, NKV_, 1.0f);

    // 4) flash attention (fp32)
    int smemf = FLASH_SMEM_FLOATS * (int)sizeof(float);
    cudaFuncSetAttribute(flash_kernel, cudaFuncAttributeMaxDynamicSharedMemorySize, smemf);
    flash_kernel<<<dim3(S_/64, B_*NH_), 256, smemf>>>(QP, KP, VP, AO);

    // 5) output projection
    {
        int n = MROWS * H_;
        split_kernel<<<(n + 255)/256, 256>>>(AO, AOhi, AOlo, n);
    }
    gemm_mma<<<dim3(H_/128, MROWS/128), 256, GEMM_SMEM>>>(AOhi, AOlo, WoThi, WoTlo, out, H_);
}

// round 14
// speedup vs baseline: 2.0902x; 1.0018x over previous
#include <cuda_runtime.h>
#include <cuda_bf16.h>
#include <math.h>
#include <stdint.h>

#define B_   2
#define S_   1024
#define H_   4096
#define NH_  32
#define NKV_ 8
#define D_   128
#define MROWS (B_*S_)   // 2048
#define KDIM 4096       // all GEMM K dims are 4096

// ------------------------- scratch (__device__ globals) --------------------
__device__ float g_QP[(size_t)MROWS*NH_*D_];
__device__ float g_KP[(size_t)MROWS*NKV_*D_];
__device__ float g_VP[(size_t)MROWS*NKV_*D_];
__device__ float g_AO[(size_t)MROWS*NH_*D_];

__device__ __nv_bfloat16 g_HShi[(size_t)MROWS*H_];
__device__ __nv_bfloat16 g_HSlo[(size_t)MROWS*H_];
__device__ __nv_bfloat16 g_AOhi[(size_t)MROWS*H_];
__device__ __nv_bfloat16 g_AOlo[(size_t)MROWS*H_];
__device__ __nv_bfloat16 g_WqThi[(size_t)H_*H_];        // [N, K] (K contiguous)
__device__ __nv_bfloat16 g_WqTlo[(size_t)H_*H_];
__device__ __nv_bfloat16 g_WkThi[(size_t)(NKV_*D_)*H_];
__device__ __nv_bfloat16 g_WkTlo[(size_t)(NKV_*D_)*H_];
__device__ __nv_bfloat16 g_WvThi[(size_t)(NKV_*D_)*H_];
__device__ __nv_bfloat16 g_WvTlo[(size_t)(NKV_*D_)*H_];
__device__ __nv_bfloat16 g_WoThi[(size_t)H_*H_];
__device__ __nv_bfloat16 g_WoTlo[(size_t)H_*H_];

// ------------------------- PTX helpers (base-target only) -------------------
__device__ __forceinline__ uint32_t smem_u32(const void* p) {
    uint32_t a;
    asm("{ .reg .u64 t; cvta.to.shared.u64 t, %1; cvt.u32.u64 %0, t; }"
        : "=r"(a) : "l"(p));
    return a;
}
__device__ __forceinline__ void cpasync16(uint32_t dst, const void* src) {
    asm volatile("cp.async.cg.shared.global [%0], [%1], 16;"
                 :: "r"(dst), "l"(src) : "memory");
}
#define CP_COMMIT()  asm volatile("cp.async.commit_group;" ::: "memory")
#define CP_WAIT(n)   asm volatile("cp.async.wait_group %0;" :: "n"(n) : "memory")

__device__ __forceinline__ void ldm4(uint32_t* r, uint32_t addr) {
    asm volatile("ldmatrix.sync.aligned.m8n8.x4.shared.b16 {%0,%1,%2,%3}, [%4];"
                 : "=r"(r[0]), "=r"(r[1]), "=r"(r[2]), "=r"(r[3]) : "r"(addr));
}
__device__ __forceinline__ void mma16816(float* d, const uint32_t* a,
                                         uint32_t b0, uint32_t b1) {
    asm volatile(
        "mma.sync.aligned.m16n8k16.row.col.f32.bf16.bf16.f32 "
        "{%0,%1,%2,%3}, {%4,%5,%6,%7}, {%8,%9}, {%0,%1,%2,%3};"
        : "+f"(d[0]), "+f"(d[1]), "+f"(d[2]), "+f"(d[3])
        : "r"(a[0]), "r"(a[1]), "r"(a[2]), "r"(a[3]), "r"(b0), "r"(b1));
}

// ------------------------- convert kernels ---------------------------------
__global__ void split_kernel(const float* __restrict__ X,
                             __nv_bfloat16* __restrict__ Hi,
                             __nv_bfloat16* __restrict__ Lo, int n)
{
    int i = blockIdx.x * blockDim.x + threadIdx.x;
    if (i >= n) return;
    float x = X[i];
    __nv_bfloat16 h = __float2bfloat16(x);
    Hi[i] = h;
    Lo[i] = __float2bfloat16(x - __bfloat162float(h));
}

// W [K,N] fp32 -> WT [N,K] bf16 hi/lo (tiled transpose)
__global__ void split_transpose_kernel(const float* __restrict__ W,
                                       __nv_bfloat16* __restrict__ Hi,
                                       __nv_bfloat16* __restrict__ Lo,
                                       int K, int N)
{
    __shared__ float tile[32][33];
    int n0 = blockIdx.x * 32, k0 = blockIdx.y * 32;
    int tx = threadIdx.x, ty = threadIdx.y;     // block (32,8)
#pragma unroll
    for (int i = 0; i < 4; i++)
        tile[ty + i*8][tx] = W[(size_t)(k0 + ty + i*8) * N + n0 + tx];
    __syncthreads();
#pragma unroll
    for (int i = 0; i < 4; i++) {
        float x = tile[tx][ty + i*8];
        __nv_bfloat16 h = __float2bfloat16(x);
        size_t o = (size_t)(n0 + ty + i*8) * K + k0 + tx;
        Hi[o] = h;
        Lo[o] = __float2bfloat16(x - __bfloat162float(h));
    }
}

// ------------------------- mma.sync split-bf16 GEMM -------------------------
// C[M,N] = A[M,K] @ B[K,N]; A as hi/lo bf16 [M,K]; B as BT hi/lo bf16 [N,K].
// CTA tile 128x128, k-chunk 32, 8 warps (2x4), warp tile 64x32.
// smem tile: 128 rows x 32 bf16 (64B rows), XOR swizzle c16 ^= (r>>1)&3.
#define TILE_BYTES 8192                  // 128 * 64B
#define STAGE_BYTES (4*TILE_BYTES)       // Ahi, Alo, Bhi, Blo
#define GEMM_SMEM (2*STAGE_BYTES)        // double buffer = 64 KB

__global__ __launch_bounds__(256) void gemm_mma(
    const __nv_bfloat16* __restrict__ Ahi, const __nv_bfloat16* __restrict__ Alo,
    const __nv_bfloat16* __restrict__ BThi, const __nv_bfloat16* __restrict__ BTlo,
    float* __restrict__ C, int N)
{
    extern __shared__ char smc[];
    const uint32_t smem0 = smem_u32(smc);
    const int t = threadIdx.x, lane = t & 31, warp = t >> 5;
    const int warp_m = warp >> 2, warp_n = warp & 3;
    const int bn0 = blockIdx.x * 128, bm0 = blockIdx.y * 128;

    const __nv_bfloat16* srcb[4] = {
        Ahi  + (size_t)bm0 * KDIM,  Alo  + (size_t)bm0 * KDIM,
        BThi + (size_t)bn0 * KDIM,  BTlo + (size_t)bn0 * KDIM };

    // per-thread cp.async decomposition: 2048 16B transfers, 8 per thread
    int ld_tile[8], ld_r[8], ld_c[8];
#pragma unroll
    for (int j = 0; j < 8; j++) {
        int g = t + j * 256;
        ld_tile[j] = g >> 9;
        int idx = g & 511;
        ld_r[j] = idx >> 2;
        ld_c[j] = idx & 3;
    }

    // ldmatrix per-lane offsets (chunk-invariant)
    uint32_t aoff[4][2], boff[2][2];
    {
        int aRow = warp_m * 64 + (lane & 15);
        int aKh  = lane >> 4;
#pragma unroll
        for (int mt = 0; mt < 4; mt++)
#pragma unroll
            for (int ks = 0; ks < 2; ks++) {
                int r = aRow + mt * 16;
                int logc = ks * 2 + aKh;
                aoff[mt][ks] = (uint32_t)(r * 64 + ((logc ^ ((r >> 1) & 3)) << 4));
            }
        int bRow = warp_n * 32 + ((lane >> 4) << 3) + (lane & 7);
        int bKh  = (lane >> 3) & 1;
#pragma unroll
        for (int np = 0; np < 2; np++)
#pragma unroll
            for (int ks = 0; ks < 2; ks++) {
                int r = bRow + np * 16;
                int logc = ks * 2 + bKh;
                boff[np][ks] = (uint32_t)(r * 64 + ((logc ^ ((r >> 1) & 3)) << 4));
            }
    }

    float acc[4][4][4];
#pragma unroll
    for (int mt = 0; mt < 4; mt++)
#pragma unroll
        for (int nt = 0; nt < 4; nt++)
#pragma unroll
            for (int k = 0; k < 4; k++) acc[mt][nt][k] = 0.f;

    auto issue_chunk = [&](int kt) {
        const int k0 = kt * 32;
        const uint32_t st = smem0 + (uint32_t)(kt & 1) * STAGE_BYTES;
#pragma unroll
        for (int j = 0; j < 8; j++) {
            const __nv_bfloat16* src =
                srcb[ld_tile[j]] + (size_t)ld_r[j] * KDIM + k0 + ld_c[j] * 8;
            uint32_t dst = st + (uint32_t)(ld_tile[j] * TILE_BYTES)
                         + (uint32_t)(ld_r[j] * 64)
                         + (uint32_t)((ld_c[j] ^ ((ld_r[j] >> 1) & 3)) << 4);
            cpasync16(dst, src);
        }
        CP_COMMIT();
    };

    const int nChunks = KDIM / 32;   // 128
    issue_chunk(0);

    for (int kt = 0; kt < nChunks; ++kt) {
        if (kt + 1 < nChunks) { issue_chunk(kt + 1); CP_WAIT(1); }
        else                  { CP_WAIT(0); }
        __syncthreads();

        const uint32_t st = smem0 + (uint32_t)(kt & 1) * STAGE_BYTES;
#pragma unroll
        for (int ks = 0; ks < 2; ks++) {
            uint32_t ah[4][4], al[4][4], bh[2][4], bl[2][4];
#pragma unroll
            for (int mt = 0; mt < 4; mt++) {
                ldm4(ah[mt], st + aoff[mt][ks]);
                ldm4(al[mt], st + TILE_BYTES + aoff[mt][ks]);
            }
#pragma unroll
            for (int np = 0; np < 2; np++) {
                ldm4(bh[np], st + 2*TILE_BYTES + boff[np][ks]);
                ldm4(bl[np], st + 3*TILE_BYTES + boff[np][ks]);
            }
#pragma unroll
            for (int mt = 0; mt < 4; mt++)
#pragma unroll
                for (int nt = 0; nt < 4; nt++) {
                    const int np = nt >> 1, ro = (nt & 1) * 2;
                    mma16816(acc[mt][nt], ah[mt], bh[np][ro], bh[np][ro+1]);
                    mma16816(acc[mt][nt], ah[mt], bl[np][ro], bl[np][ro+1]);
                    mma16816(acc[mt][nt], al[mt], bh[np][ro], bh[np][ro+1]);
                }
        }
        __syncthreads();
    }

    // epilogue
    const int gid = lane >> 2, tig = lane & 3;
#pragma unroll
    for (int mt = 0; mt < 4; mt++) {
        const int row = bm0 + warp_m * 64 + mt * 16 + gid;
#pragma unroll
        for (int nt = 0; nt < 4; nt++) {
            const int col = bn0 + warp_n * 32 + nt * 8 + tig * 2;
            *(float2*)&C[(size_t)row * N + col] =
                make_float2(acc[mt][nt][0], acc[mt][nt][1]);
            *(float2*)&C[(size_t)(row + 8) * N + col] =
                make_float2(acc[mt][nt][2], acc[mt][nt][3]);
        }
    }
}

// ------------------------- RoPE --------------------------------------------
__global__ void rope_scale_kernel(float* __restrict__ X,
                                  const float* __restrict__ cosT,
                                  const float* __restrict__ sinT,
                                  int nheads, float scale)
{
    int idx = blockIdx.x * blockDim.x + threadIdx.x;
    int total = MROWS * nheads * (D_/2);
    if (idx >= total) return;
    int d    = idx & 63;
    int rest = idx >> 6;
    int h = rest % nheads;
    int m = rest / nheads;
    float* p = X + ((size_t)m * nheads + h) * D_;
    float q1 = p[d], q2 = p[d+64];
    float c1 = cosT[m*D_ + d],      s1 = sinT[m*D_ + d];
    float c2 = cosT[m*D_ + d + 64], s2 = sinT[m*D_ + d + 64];
    p[d]    = (q1*c1 - q2*s1) * scale;
    p[d+64] = (q2*c2 + q1*s2) * scale;
}

// ------------------------- flash attention (fp32, proven) -------------------
#define QS_LD 132
#define KS_LD 132
#define PS_LD 68
#define FLASH_SMEM_FLOATS (64*QS_LD + 64*KS_LD + 64*128 + 64*PS_LD)

__global__ __launch_bounds__(256) void flash_kernel(
    const float* __restrict__ Q, const float* __restrict__ K,
    const float* __restrict__ V, float* __restrict__ O)
{
    extern __shared__ float smf[];
    float* Qs = smf;
    float* Ks = Qs + 64*QS_LD;
    float* Vs = Ks + 64*KS_LD;
    float* Ps = Vs + 64*128;

    const int t  = threadIdx.x;
    const int tx = t & 15, ty = t >> 4;
    const int m0 = blockIdx.x * 64;
    const int bh = blockIdx.y;
    const int b  = bh >> 5;
    const int h  = bh & 31;
    const int kvh = h >> 2;

    const float* Qb = Q + (size_t)b*S_*NH_*D_  + h*D_;
    const float* Kb = K + (size_t)b*S_*NKV_*D_ + kvh*D_;
    const float* Vb = V + (size_t)b*S_*NKV_*D_ + kvh*D_;

    for (int l = t; l < 64*32; l += 256) {
        int r = l >> 5, c4 = (l & 31) * 4;
        *(float4*)&Qs[r*QS_LD + c4] = *(const float4*)(Qb + (size_t)(m0 + r)*(NH_*D_) + c4);
    }

    float acc[4][8];
#pragma unroll
    for (int i = 0; i < 4; i++)
#pragma unroll
        for (int j = 0; j < 8; j++) acc[i][j] = 0.f;
    float mi[4] = {-1e30f,-1e30f,-1e30f,-1e30f};
    float li[4] = {0.f,0.f,0.f,0.f};

    const int nT = blockIdx.x + 1;
    for (int itt = 0; itt < nT; ++itt) {
        int n0 = itt * 64;
        for (int l = t; l < 64*32; l += 256) {
            int r = l >> 5, c4 = (l & 31) * 4;
            *(float4*)&Ks[r*KS_LD + c4] = *(const float4*)(Kb + (size_t)(n0 + r)*(NKV_*D_) + c4);
            *(float4*)&Vs[r*128 + c4]   = *(const float4*)(Vb + (size_t)(n0 + r)*(NKV_*D_) + c4);
        }
        __syncthreads();

        float s[4][4];
#pragma unroll
        for (int i = 0; i < 4; i++)
#pragma unroll
            for (int j = 0; j < 4; j++) s[i][j] = 0.f;
        for (int k4 = 0; k4 < 32; k4++) {
            float4 qa[4], kb[4];
#pragma unroll
            for (int i = 0; i < 4; i++) qa[i] = *(float4*)&Qs[(ty*4+i)*QS_LD + k4*4];
#pragma unroll
            for (int j = 0; j < 4; j++) kb[j] = *(float4*)&Ks[(tx*4+j)*KS_LD + k4*4];
#pragma unroll
            for (int i = 0; i < 4; i++)
#pragma unroll
                for (int j = 0; j < 4; j++)
                    s[i][j] += qa[i].x*kb[j].x + qa[i].y*kb[j].y
                             + qa[i].z*kb[j].z + qa[i].w*kb[j].w;
        }
        if (n0 == m0) {
#pragma unroll
            for (int i = 0; i < 4; i++)
#pragma unroll
                for (int j = 0; j < 4; j++)
                    if (tx*4 + j > ty*4 + i) s[i][j] = -1e30f;
        }

#pragma unroll
        for (int i = 0; i < 4; i++) {
            float ml = fmaxf(fmaxf(s[i][0], s[i][1]), fmaxf(s[i][2], s[i][3]));
#pragma unroll
            for (int off = 8; off > 0; off >>= 1)
                ml = fmaxf(ml, __shfl_xor_sync(0xffffffffu, ml, off));
            float mnew  = fmaxf(mi[i], ml);
            float alpha = __expf(mi[i] - mnew);
            mi[i] = mnew;
            float4 pr;
            pr.x = __expf(s[i][0] - mnew); pr.y = __expf(s[i][1] - mnew);
            pr.z = __expf(s[i][2] - mnew); pr.w = __expf(s[i][3] - mnew);
            float rsum = pr.x + pr.y + pr.z + pr.w;
            *(float4*)&Ps[(ty*4+i)*PS_LD + tx*4] = pr;
#pragma unroll
            for (int off = 8; off > 0; off >>= 1)
                rsum += __shfl_xor_sync(0xffffffffu, rsum, off);
            li[i] = li[i]*alpha + rsum;
#pragma unroll
            for (int j = 0; j < 8; j++) acc[i][j] *= alpha;
        }
        __syncthreads();

        for (int k4 = 0; k4 < 16; k4++) {
            float4 p4[4];
#pragma unroll
            for (int i = 0; i < 4; i++) p4[i] = *(float4*)&Ps[(ty*4+i)*PS_LD + k4*4];
#pragma unroll
            for (int kk = 0; kk < 4; kk++) {
                float4 v0 = *(float4*)&Vs[(k4*4+kk)*128 + tx*8];
                float4 v1 = *(float4*)&Vs[(k4*4+kk)*128 + tx*8 + 4];
#pragma unroll
                for (int i = 0; i < 4; i++) {
                    float pv = (kk==0) ? p4[i].x : (kk==1) ? p4[i].y
                             : (kk==2) ? p4[i].z : p4[i].w;
                    acc[i][0] += pv*v0.x; acc[i][1] += pv*v0.y;
                    acc[i][2] += pv*v0.z; acc[i][3] += pv*v0.w;
                    acc[i][4] += pv*v1.x; acc[i][5] += pv*v1.y;
                    acc[i][6] += pv*v1.z; acc[i][7] += pv*v1.w;
                }
            }
        }
        __syncthreads();
    }

#pragma unroll
    for (int i = 0; i < 4; i++) {
        float inv = 1.0f / li[i];
        int r = m0 + ty*4 + i;
        float* op = O + (size_t)(b*S_ + r)*(NH_*D_) + h*D_ + tx*8;
        *(float4*)&op[0] = make_float4(acc[i][0]*inv, acc[i][1]*inv, acc[i][2]*inv, acc[i][3]*inv);
        *(float4*)&op[4] = make_float4(acc[i][4]*inv, acc[i][5]*inv, acc[i][6]*inv, acc[i][7]*inv);
    }
}

// ------------------------- kernel_launch -----------------------------------
// inputs: 0 hidden_states, 1 cos, 2 sin, 3 attention_mask (causal, applied
// analytically), 4 Wq, 5 Wk, 6 Wv, 7 Wo
extern "C" void kernel_launch(void* const* d_in, const int* in_sizes, int n_in,
                              void* d_out, int out_size)
{
    (void)in_sizes; (void)out_size;
    if (n_in < 8) return;
    const float* hs   = (const float*)d_in[0];
    const float* cosT = (const float*)d_in[1];
    const float* sinT = (const float*)d_in[2];
    const float* Wq   = (const float*)d_in[4];
    const float* Wk   = (const float*)d_in[5];
    const float* Wv   = (const float*)d_in[6];
    const float* Wo   = (const float*)d_in[7];
    float* out = (float*)d_out;

    float *QP, *KP, *VP, *AO;
    cudaGetSymbolAddress((void**)&QP, g_QP);
    cudaGetSymbolAddress((void**)&KP, g_KP);
    cudaGetSymbolAddress((void**)&VP, g_VP);
    cudaGetSymbolAddress((void**)&AO, g_AO);
    __nv_bfloat16 *HShi, *HSlo, *AOhi, *AOlo;
    __nv_bfloat16 *WqThi, *WqTlo, *WkThi, *WkTlo, *WvThi, *WvTlo, *WoThi, *WoTlo;
    cudaGetSymbolAddress((void**)&HShi, g_HShi);
    cudaGetSymbolAddress((void**)&HSlo, g_HSlo);
    cudaGetSymbolAddress((void**)&AOhi, g_AOhi);
    cudaGetSymbolAddress((void**)&AOlo, g_AOlo);
    cudaGetSymbolAddress((void**)&WqThi, g_WqThi);
    cudaGetSymbolAddress((void**)&WqTlo, g_WqTlo);
    cudaGetSymbolAddress((void**)&WkThi, g_WkThi);
    cudaGetSymbolAddress((void**)&WkTlo, g_WkTlo);
    cudaGetSymbolAddress((void**)&WvThi, g_WvThi);
    cudaGetSymbolAddress((void**)&WvTlo, g_WvTlo);
    cudaGetSymbolAddress((void**)&WoThi, g_WoThi);
    cudaGetSymbolAddress((void**)&WoTlo, g_WoTlo);

    // 1) split conversions
    {
        int n = MROWS * H_;
        split_kernel<<<(n + 255)/256, 256>>>(hs, HShi, HSlo, n);
    }
    split_transpose_kernel<<<dim3(H_/32, H_/32),        dim3(32,8)>>>(Wq, WqThi, WqTlo, H_, H_);
    split_transpose_kernel<<<dim3((NKV_*D_)/32, H_/32), dim3(32,8)>>>(Wk, WkThi, WkTlo, H_, NKV_*D_);
    split_transpose_kernel<<<dim3((NKV_*D_)/32, H_/32), dim3(32,8)>>>(Wv, WvThi, WvTlo, H_, NKV_*D_);
    split_transpose_kernel<<<dim3(H_/32, H_/32),        dim3(32,8)>>>(Wo, WoThi, WoTlo, H_, H_);

    // 2) projections on tensor cores (mma.sync split-bf16)
    cudaFuncSetAttribute(gemm_mma, cudaFuncAttributeMaxDynamicSharedMemorySize, GEMM_SMEM);
    gemm_mma<<<dim3((NH_*D_)/128,  MROWS/128), 256, GEMM_SMEM>>>(HShi, HSlo, WqThi, WqTlo, QP, NH_*D_);
    gemm_mma<<<dim3((NKV_*D_)/128, MROWS/128), 256, GEMM_SMEM>>>(HShi, HSlo, WkThi, WkTlo, KP, NKV_*D_);
    gemm_mma<<<dim3((NKV_*D_)/128, MROWS/128), 256, GEMM_SMEM>>>(HShi, HSlo, WvThi, WvTlo, VP, NKV_*D_);

    // 3) RoPE (fold 1/sqrt(D) into Q)
    const float scale = 0.08838834764831845f;
    rope_scale_kernel<<<(MROWS*NH_*64  + 255)/256, 256>>>(QP, cosT, sinT, NH_,  scale);
    rope_scale_kernel<<<(MROWS*NKV_*64 + 255)/256, 256>>>(KP, cosT, sinT, NKV_, 1.0f);

    // 4) flash attention (fp32)
    int smemf = FLASH_SMEM_FLOATS * (int)sizeof(float);
    cudaFuncSetAttribute(flash_kernel, cudaFuncAttributeMaxDynamicSharedMemorySize, smemf);
    flash_kernel<<<dim3(S_/64, B_*NH_), 256, smemf>>>(QP, KP, VP, AO);

    // 5) output projection
    {
        int n = MROWS * H_;
        split_kernel<<<(n + 255)/256, 256>>>(AO, AOhi, AOlo, n);
    }
    gemm_mma<<<dim3(H_/128, MROWS/128), 256, GEMM_SMEM>>>(AOhi, AOlo, WoThi, WoTlo, out, H_);
}